// round 6
// baseline (speedup 1.0000x reference)
#include <cuda_runtime.h>
#include <cuda_bf16.h>
#include <mma.h>
#include <math.h>

using namespace nvcuda;

#define Bb   4
#define Tt   2048
#define Dd   1024
#define Hh   16
#define DhD  64
#define SEG  256
#define NSEG 8
#define BT   (Bb*Tt)      // 8192
#define BH   (Bb*Hh)      // 64

// ---------------- scratch (device globals; no allocations allowed) ----------
__device__ __align__(16) float g_q[BT*Dd];
__device__ __align__(16) float g_k[BT*Dd];
__device__ __align__(16) float g_v[BT*Dd];
__device__ __align__(16) float g_u[BT*Dd];
__device__ __align__(16) float g_y[BT*Dd];
__device__ __align__(16) float g_Sseg[BH*NSEG*DhD*DhD];
__device__ __align__(16) float g_cS  [BH*NSEG*DhD*DhD];
__device__ __align__(16) float g_cctx[BH*NSEG*DhD];

// bf16 split operands for tensor-core GEMMs
__device__ __align__(16) __nv_bfloat16 g_xhi[BT*Dd];
__device__ __align__(16) __nv_bfloat16 g_xlo[BT*Dd];
__device__ __align__(16) __nv_bfloat16 g_yhi[BT*Dd];
__device__ __align__(16) __nv_bfloat16 g_ylo[BT*Dd];
__device__ __align__(16) __nv_bfloat16 g_whi[5*Dd*Dd];
__device__ __align__(16) __nv_bfloat16 g_wlo[5*Dd*Dd];

// ---------------- fp32 -> (bf16 hi, bf16 lo) split ---------------------------
__global__ __launch_bounds__(256) void cvt_split(
    const float4* __restrict__ in,
    __nv_bfloat16* __restrict__ hi, __nv_bfloat16* __restrict__ lo, int n4)
{
    int i = blockIdx.x * 256 + threadIdx.x;
    if (i >= n4) return;
    float4 v = in[i];
    __nv_bfloat162 h01, h23, l01, l23;
    h01.x = __float2bfloat16(v.x);
    h01.y = __float2bfloat16(v.y);
    h23.x = __float2bfloat16(v.z);
    h23.y = __float2bfloat16(v.w);
    l01.x = __float2bfloat16(v.x - __bfloat162float(h01.x));
    l01.y = __float2bfloat16(v.y - __bfloat162float(h01.y));
    l23.x = __float2bfloat16(v.z - __bfloat162float(h23.x));
    l23.y = __float2bfloat16(v.w - __bfloat162float(h23.y));
    ((__nv_bfloat162*)&hi[4*i])[0] = h01;
    ((__nv_bfloat162*)&hi[4*i])[1] = h23;
    ((__nv_bfloat162*)&lo[4*i])[0] = l01;
    ((__nv_bfloat162*)&lo[4*i])[1] = l23;
}

// all 5 weight matrices in one launch
__global__ __launch_bounds__(256) void cvt_w(
    const float4* __restrict__ Wq, const float4* __restrict__ Wk,
    const float4* __restrict__ Wv, const float4* __restrict__ Wu,
    const float4* __restrict__ Wo)
{
    int g = blockIdx.x * 256 + threadIdx.x;   // 5 * 262144 float4s
    int wsel = g >> 18;
    int off  = g & 262143;
    const float4* src = (wsel == 0) ? Wq : (wsel == 1) ? Wk :
                        (wsel == 2) ? Wv : (wsel == 3) ? Wu : Wo;
    float4 v = src[off];
    long base = (long)wsel * Dd * Dd + 4l * off;
    __nv_bfloat162 h01, h23, l01, l23;
    h01.x = __float2bfloat16(v.x);
    h01.y = __float2bfloat16(v.y);
    h23.x = __float2bfloat16(v.z);
    h23.y = __float2bfloat16(v.w);
    l01.x = __float2bfloat16(v.x - __bfloat162float(h01.x));
    l01.y = __float2bfloat16(v.y - __bfloat162float(h01.y));
    l23.x = __float2bfloat16(v.z - __bfloat162float(h23.x));
    l23.y = __float2bfloat16(v.w - __bfloat162float(h23.y));
    ((__nv_bfloat162*)&g_whi[base])[0] = h01;
    ((__nv_bfloat162*)&g_whi[base])[1] = h23;
    ((__nv_bfloat162*)&g_wlo[base])[0] = l01;
    ((__nv_bfloat162*)&g_wlo[base])[1] = l23;
}

// ---------------- tensor-core GEMM: C = A@B, 3-term bf16 split ---------------
// 128x128 block tile, BK=32, 256 threads (8 warps, 4x2), warp tile 32x64.
__device__ __forceinline__ void gemm_tc_body(
    const __nv_bfloat16* __restrict__ Ahi, const __nv_bfloat16* __restrict__ Alo,
    const __nv_bfloat16* __restrict__ Bhi, const __nv_bfloat16* __restrict__ Blo,
    float* __restrict__ C, int M, int N, int K, int brow, int bcol)
{
    __shared__ __align__(32) __nv_bfloat16 As[2][128][40];
    __shared__ __align__(32) __nv_bfloat16 Bs[2][32][136];

    const int tid  = threadIdx.x;
    const int warp = tid >> 5;
    const int wm   = warp & 3;    // 0..3  -> 32-row slab
    const int wn   = warp >> 2;   // 0..1  -> 64-col slab

    wmma::fragment<wmma::accumulator, 16, 16, 16, float> acc[2][4];
#pragma unroll
    for (int i = 0; i < 2; i++)
#pragma unroll
        for (int j = 0; j < 4; j++) wmma::fill_fragment(acc[i][j], 0.f);

    for (int k0 = 0; k0 < K; k0 += 32) {
        __syncthreads();
#pragma unroll
        for (int j = 0; j < 2; j++) {
            int c  = tid + j * 256;
            int r  = c >> 2, cc = (c & 3) << 3;        // A: 128 rows x 32 cols
            *(uint4*)&As[0][r][cc] = *(const uint4*)&Ahi[(long)(brow + r) * K + k0 + cc];
            *(uint4*)&As[1][r][cc] = *(const uint4*)&Alo[(long)(brow + r) * K + k0 + cc];
            int rb = c >> 4, cb = (c & 15) << 3;       // B: 32 rows x 128 cols
            *(uint4*)&Bs[0][rb][cb] = *(const uint4*)&Bhi[(long)(k0 + rb) * N + bcol + cb];
            *(uint4*)&Bs[1][rb][cb] = *(const uint4*)&Blo[(long)(k0 + rb) * N + bcol + cb];
        }
        __syncthreads();

#pragma unroll
        for (int kk = 0; kk < 32; kk += 16) {
            wmma::fragment<wmma::matrix_a, 16, 16, 16, __nv_bfloat16, wmma::row_major> ah[2], al[2];
            wmma::fragment<wmma::matrix_b, 16, 16, 16, __nv_bfloat16, wmma::row_major> bh[4], bl[4];
#pragma unroll
            for (int i = 0; i < 2; i++) {
                wmma::load_matrix_sync(ah[i], &As[0][wm * 32 + i * 16][kk], 40);
                wmma::load_matrix_sync(al[i], &As[1][wm * 32 + i * 16][kk], 40);
            }
#pragma unroll
            for (int j = 0; j < 4; j++) {
                wmma::load_matrix_sync(bh[j], &Bs[0][kk][wn * 64 + j * 16], 136);
                wmma::load_matrix_sync(bl[j], &Bs[1][kk][wn * 64 + j * 16], 136);
            }
#pragma unroll
            for (int i = 0; i < 2; i++)
#pragma unroll
                for (int j = 0; j < 4; j++) {
                    wmma::mma_sync(acc[i][j], ah[i], bh[j], acc[i][j]);
                    wmma::mma_sync(acc[i][j], ah[i], bl[j], acc[i][j]);
                    wmma::mma_sync(acc[i][j], al[i], bh[j], acc[i][j]);
                }
        }
    }

#pragma unroll
    for (int i = 0; i < 2; i++)
#pragma unroll
        for (int j = 0; j < 4; j++)
            wmma::store_matrix_sync(
                &C[(long)(brow + wm * 32 + i * 16) * N + bcol + wn * 64 + j * 16],
                acc[i][j], N, wmma::mem_row_major);
}

// fused q/k/v/u projections: z selects weight slab + destination
__global__ __launch_bounds__(256) void proj4_tc()
{
    int z = blockIdx.z;
    const __nv_bfloat16* Bh = g_whi + (long)z * Dd * Dd;
    const __nv_bfloat16* Bl = g_wlo + (long)z * Dd * Dd;
    float* Cd = (z == 0) ? g_q : (z == 1) ? g_k : (z == 2) ? g_v : g_u;
    gemm_tc_body(g_xhi, g_xlo, Bh, Bl, Cd, BT, Dd, Dd,
                 blockIdx.y * 128, blockIdx.x * 128);
}

__global__ __launch_bounds__(256) void gemm_out_tc(float* __restrict__ out)
{
    gemm_tc_body(g_yhi, g_ylo, g_whi + 4l * Dd * Dd, g_wlo + 4l * Dd * Dd,
                 out, BT, Dd, Dd, blockIdx.y * 128, blockIdx.x * 128);
}

// ---------------- per-segment sums: Sseg[b,h,s] = sum_t k (x) v; cctx = sum k
__global__ __launch_bounds__(256) void seg_sums()
{
    const int bx = blockIdx.x;
    const int s  = bx & (NSEG - 1);
    const int bh = bx >> 3;
    const int b  = bh >> 4;
    const int h  = bh & 15;
    const int tid = threadIdx.x;
    const int d  = tid >> 2;
    const int e0 = (tid & 3) << 4;

    __shared__ __align__(16) float Ks[32][64];
    __shared__ __align__(16) float Vs[32][64];

    float acc[16];
#pragma unroll
    for (int i = 0; i < 16; i++) acc[i] = 0.f;
    float ctx = 0.f;

    for (int tt = 0; tt < SEG; tt += 32) {
        __syncthreads();
        for (int i = tid; i < 512; i += 256) {
            int tok = i >> 4, c4 = (i & 15) << 2;
            long g = ((long)(b * Tt + s * SEG + tt + tok) * Hh + h) * DhD + c4;
            *(float4*)&Ks[tok][c4] = *(const float4*)&g_k[g];
            *(float4*)&Vs[tok][c4] = *(const float4*)&g_v[g];
        }
        __syncthreads();
#pragma unroll
        for (int j = 0; j < 32; j++) {
            float kd = Ks[j][d];
            ctx += kd;
            const float4* vr = (const float4*)&Vs[j][e0];
#pragma unroll
            for (int q4 = 0; q4 < 4; q4++) {
                float4 vv = vr[q4];
                acc[4*q4+0] += kd * vv.x;
                acc[4*q4+1] += kd * vv.y;
                acc[4*q4+2] += kd * vv.z;
                acc[4*q4+3] += kd * vv.w;
            }
        }
    }
    long base = ((long)(bh * NSEG + s) * DhD + d) * DhD + e0;
#pragma unroll
    for (int q4 = 0; q4 < 4; q4++)
        *(float4*)&g_Sseg[base + 4*q4] =
            make_float4(acc[4*q4], acc[4*q4+1], acc[4*q4+2], acc[4*q4+3]);
    if ((tid & 3) == 0) g_cctx[(bh * NSEG + s) * DhD + d] = ctx;
}

// ---------------- prefix over segments ---------------------------------------
__global__ __launch_bounds__(256) void seg_prefix()
{
    const int bh = blockIdx.x;
    for (int i = threadIdx.x; i < DhD * DhD; i += 256) {
        float run = 0.f;
#pragma unroll
        for (int s = 0; s < NSEG; s++) {
            long idx = ((long)(bh * NSEG + s)) * (DhD * DhD) + i;
            run += g_Sseg[idx];
            g_cS[idx] = run;
        }
    }
}

// ---------------- attention/mixing: one block per (b,h,seg), thread = token -
__global__ __launch_bounds__(256) void attn_kernel()
{
    const int bx  = blockIdx.x;
    const int seg = bx & (NSEG - 1);
    const int bh  = bx >> 3;
    const int b   = bh >> 4;
    const int h   = bh & 15;
    const int t   = threadIdx.x;
    const int tg  = seg * SEG + t;
    const int cur = seg;

    __shared__ __align__(16) float Ks[64][64];
    __shared__ __align__(16) float Vs[64][64];
    __shared__ __align__(16) float Cs[8][64];
    __shared__ float Wsm[8][256];

    const long rowbase = ((long)(b * Tt + tg) * Hh + h) * DhD;

    // ---------- phase 1: scores ----------
    float sc[8];
    float ons = 0.f;
    {
        float ureg[64];
        const float4* up = (const float4*)&g_u[rowbase];
#pragma unroll
        for (int i = 0; i < 16; i++) {
            float4 w4 = up[i];
            ureg[4*i] = w4.x; ureg[4*i+1] = w4.y; ureg[4*i+2] = w4.z; ureg[4*i+3] = w4.w;
        }
        for (int i = t; i < cur * 64; i += 256)
            Cs[i >> 6][i & 63] = g_cctx[(bh * NSEG + (i >> 6)) * DhD + (i & 63)];
        __syncthreads();
#pragma unroll
        for (int s = 0; s < 8; s++) {
            float a = 0.f;
            if (s < cur) {
                const float4* cp = (const float4*)Cs[s];
#pragma unroll
                for (int j = 0; j < 16; j++) {
                    float4 c4 = cp[j];
                    a += ureg[4*j]*c4.x + ureg[4*j+1]*c4.y + ureg[4*j+2]*c4.z + ureg[4*j+3]*c4.w;
                }
            }
            sc[s] = a;
        }
        for (int tile = 0; tile < 4; tile++) {
            __syncthreads();
            for (int i = t; i < 1024; i += 256) {
                int tok = i >> 4, c4 = (i & 15) << 2;
                long g = ((long)(b * Tt + seg * SEG + tile * 64 + tok) * Hh + h) * DhD + c4;
                *(float4*)&Ks[tok][c4] = *(const float4*)&g_k[g];
            }
            __syncthreads();
            int lim = t - tile * 64;
            if (lim >= 0) {
                int n = lim < 63 ? lim : 63;
                for (int tp = 0; tp <= n; tp++) {
                    const float4* kr = (const float4*)Ks[tp];
                    float a = 0.f;
#pragma unroll
                    for (int j = 0; j < 16; j++) {
                        float4 k4 = kr[j];
                        a += ureg[4*j]*k4.x + ureg[4*j+1]*k4.y + ureg[4*j+2]*k4.z + ureg[4*j+3]*k4.w;
                    }
                    ons += a;
                }
            }
        }
    }

    // ---------- softmax over [sc[0..cur-1], ons] ----------
    float wcur;
    if (cur == 0) {
        wcur = 1.f;
    } else {
        float m = ons;
#pragma unroll
        for (int s = 0; s < 8; s++) if (s < cur && sc[s] > m) m = sc[s];
        float eon = expf(ons - m);
        float denom = eon;
#pragma unroll
        for (int s = 0; s < 8; s++) {
            if (s < cur) { float e = expf(sc[s] - m); sc[s] = e; denom += e; }
        }
        float inv = 1.f / denom;
        wcur = eon * inv;
#pragma unroll
        for (int s = 0; s < 8; s++)
            if (s < cur) Wsm[s][t] = sc[s] * inv + ((s == cur - 1) ? wcur : 0.f);
    }

    // ---------- phase 2: output ----------
    float4 q4r[16];
    {
        const float4* qp = (const float4*)&g_q[rowbase];
#pragma unroll
        for (int i = 0; i < 16; i++) q4r[i] = qp[i];
    }
    float outr[64];
#pragma unroll
    for (int i = 0; i < 64; i++) outr[i] = 0.f;

    for (int s = 0; s < cur; s++) {
        __syncthreads();
        for (int i = t; i < 1024; i += 256) {
            int dd = i >> 4, c4 = (i & 15) << 2;
            *(float4*)&Ks[dd][c4] =
                *(const float4*)&g_cS[((long)(bh * NSEG + s)) * (DhD*DhD) + dd * 64 + c4];
        }
        __syncthreads();
        float ws = Wsm[s][t];
#pragma unroll
        for (int d4 = 0; d4 < 16; d4++) {
            float4 qv = q4r[d4];
            float fq[4] = {ws*qv.x, ws*qv.y, ws*qv.z, ws*qv.w};
#pragma unroll
            for (int c = 0; c < 4; c++) {
                float f = fq[c];
                const float4* sr = (const float4*)Ks[4*d4 + c];
#pragma unroll
                for (int e = 0; e < 16; e++) {
                    float4 s4 = sr[e];
                    outr[4*e+0] += f * s4.x;
                    outr[4*e+1] += f * s4.y;
                    outr[4*e+2] += f * s4.z;
                    outr[4*e+3] += f * s4.w;
                }
            }
        }
    }

    for (int tile = 0; tile < 4; tile++) {
        __syncthreads();
        for (int i = t; i < 1024; i += 256) {
            int tok = i >> 4, c4 = (i & 15) << 2;
            long g = ((long)(b * Tt + seg * SEG + tile * 64 + tok) * Hh + h) * DhD + c4;
            *(float4*)&Ks[tok][c4] = *(const float4*)&g_k[g];
            *(float4*)&Vs[tok][c4] = *(const float4*)&g_v[g];
        }
        __syncthreads();
        int lim = t - tile * 64;
        if (lim >= 0) {
            int n = lim < 63 ? lim : 63;
            for (int tp = 0; tp <= n; tp++) {
                const float4* kr = (const float4*)Ks[tp];
                float a = 0.f;
#pragma unroll
                for (int j = 0; j < 16; j++) {
                    float4 k4 = kr[j];
                    a += q4r[j].x*k4.x + q4r[j].y*k4.y + q4r[j].z*k4.z + q4r[j].w*k4.w;
                }
                float f = wcur * a;
                const float4* vr = (const float4*)Vs[tp];
#pragma unroll
                for (int e = 0; e < 16; e++) {
                    float4 v4 = vr[e];
                    outr[4*e+0] += f * v4.x;
                    outr[4*e+1] += f * v4.y;
                    outr[4*e+2] += f * v4.z;
                    outr[4*e+3] += f * v4.w;
                }
            }
        }
    }

    float4* yp = (float4*)&g_y[rowbase];
#pragma unroll
    for (int e = 0; e < 16; e++)
        yp[e] = make_float4(outr[4*e], outr[4*e+1], outr[4*e+2], outr[4*e+3]);
}

// ---------------- launch ----------------------------------------------------
extern "C" void kernel_launch(void* const* d_in, const int* in_sizes, int n_in,
                              void* d_out, int out_size)
{
    const float* x  = (const float*)d_in[0];
    const float* Wq = (const float*)d_in[1];
    const float* Wk = (const float*)d_in[2];
    const float* Wv = (const float*)d_in[3];
    const float* Wu = (const float*)d_in[4];
    const float* Wo = (const float*)d_in[5];
    float* out = (float*)d_out;

    __nv_bfloat16 *pxh, *pxl, *pyh, *pyl;
    float* pyf;
    cudaGetSymbolAddress((void**)&pxh, g_xhi);
    cudaGetSymbolAddress((void**)&pxl, g_xlo);
    cudaGetSymbolAddress((void**)&pyh, g_yhi);
    cudaGetSymbolAddress((void**)&pyl, g_ylo);
    cudaGetSymbolAddress((void**)&pyf, g_y);

    const int N4 = BT * Dd / 4;                    // 2097152
    cvt_split<<<N4 / 256, 256>>>((const float4*)x, pxh, pxl, N4);
    cvt_w<<<5 * (Dd * Dd / 4) / 256, 256>>>(
        (const float4*)Wq, (const float4*)Wk, (const float4*)Wv,
        (const float4*)Wu, (const float4*)Wo);

    dim3 gp(Dd / 128, BT / 128, 4);                // (8, 64, 4)
    proj4_tc<<<gp, 256>>>();

    seg_sums  <<<BH * NSEG, 256>>>();
    seg_prefix<<<BH,        256>>>();
    attn_kernel<<<BH * NSEG, 256>>>();

    cvt_split<<<N4 / 256, 256>>>((const float4*)pyf, pyh, pyl, N4);

    dim3 gg(Dd / 128, BT / 128);                   // (8, 64)
    gemm_out_tc<<<gg, 256>>>(out);
}

// round 11
// speedup vs baseline: 1.3300x; 1.3300x over previous
#include <cuda_runtime.h>
#include <cuda_bf16.h>
#include <math.h>
#include <stdint.h>

#define Bb   4
#define Tt   2048
#define Dd   1024
#define Hh   16
#define DhD  64
#define SEG  256
#define NSEG 8
#define BT   (Bb*Tt)      // 8192
#define BH   (Bb*Hh)      // 64

#define SWZ(o) ((o) ^ ((((o) >> 3)) & 0x70))

// idesc kind::f16 cg1: F32 accum, BF16 a/b, N=128, M=128
#define IDESC 0x8200490u

// tcgen05 is only available on arch-SPECIFIC targets (sm_103a / sm_100a).
// The harness also builds a base-family compute_103 PTX pass; that pass gets
// a SIMT fallback so ptxas never sees tcgen05 for a base target.
#if defined(__CUDA_ARCH_FEAT_SM103_ALL) || defined(__CUDA_ARCH_FEAT_SM100_ALL) || defined(__CUDA_ARCH_SPECIFIC__)
#define TC_OK 1
#else
#define TC_OK 0
#endif

// ---------------- scratch (device globals; no allocations allowed) ----------
__device__ __align__(16) float g_q[BT*Dd];
__device__ __align__(16) float g_k[BT*Dd];
__device__ __align__(16) float g_v[BT*Dd];
__device__ __align__(16) float g_u[BT*Dd];
__device__ __align__(16) float g_y[BT*Dd];
__device__ __align__(16) float g_Sseg[BH*NSEG*DhD*DhD];
__device__ __align__(16) float g_cS  [BH*NSEG*DhD*DhD];
__device__ __align__(16) float g_cctx[BH*NSEG*DhD];

// bf16 split operands (weights stored TRANSPOSED: [N][K] K-major)
__device__ __align__(16) __nv_bfloat16 g_xhi[BT*Dd];
__device__ __align__(16) __nv_bfloat16 g_xlo[BT*Dd];
__device__ __align__(16) __nv_bfloat16 g_yhi[BT*Dd];
__device__ __align__(16) __nv_bfloat16 g_ylo[BT*Dd];
__device__ __align__(16) __nv_bfloat16 g_whi[5*Dd*Dd];
__device__ __align__(16) __nv_bfloat16 g_wlo[5*Dd*Dd];

// ---------------- small helpers ---------------------------------------------
__device__ __forceinline__ uint32_t smem_u32(const void* p) {
    uint32_t a;
    asm("{ .reg .u64 t; cvta.to.shared.u64 t, %1; cvt.u32.u64 %0, t; }"
        : "=r"(a) : "l"(p));
    return a;
}

#if TC_OK
__device__ __forceinline__ void mma_f16_ss(uint32_t d, uint64_t ad, uint64_t bd,
                                           uint32_t idesc, uint32_t en) {
    asm volatile(
        "{\n\t.reg .pred p;\n\tsetp.ne.u32 p, %5, 0;\n\t"
        "tcgen05.mma.cta_group::1.kind::f16 [%0], %1, %2, %3, {%4,%4,%4,%4}, p;\n\t}"
        :: "r"(d), "l"(ad), "l"(bd), "r"(idesc), "r"(0u), "r"(en) : "memory");
}

__device__ __forceinline__ void mbar_wait(uint32_t mbar, int parity) {
    asm volatile(
        "{\n\t.reg .pred P;\n\t"
        "LAB_%=:\n\t"
        "mbarrier.try_wait.parity.acquire.cta.shared::cta.b64 P, [%0], %1;\n\t"
        "@!P bra LAB_%=;\n\t}"
        :: "r"(mbar), "r"(parity) : "memory");
}

__device__ __forceinline__ void ldtm32(uint32_t* r, uint32_t addr) {
    asm volatile(
        "tcgen05.ld.sync.aligned.32x32b.x32.b32 "
        "{%0, %1, %2, %3, %4, %5, %6, %7, "
        " %8, %9, %10, %11, %12, %13, %14, %15, "
        " %16, %17, %18, %19, %20, %21, %22, %23, "
        " %24, %25, %26, %27, %28, %29, %30, %31}, [%32];"
        : "=r"(r[0]),  "=r"(r[1]),  "=r"(r[2]),  "=r"(r[3]),
          "=r"(r[4]),  "=r"(r[5]),  "=r"(r[6]),  "=r"(r[7]),
          "=r"(r[8]),  "=r"(r[9]),  "=r"(r[10]), "=r"(r[11]),
          "=r"(r[12]), "=r"(r[13]), "=r"(r[14]), "=r"(r[15]),
          "=r"(r[16]), "=r"(r[17]), "=r"(r[18]), "=r"(r[19]),
          "=r"(r[20]), "=r"(r[21]), "=r"(r[22]), "=r"(r[23]),
          "=r"(r[24]), "=r"(r[25]), "=r"(r[26]), "=r"(r[27]),
          "=r"(r[28]), "=r"(r[29]), "=r"(r[30]), "=r"(r[31])
        : "r"(addr));
}
#endif

// ---------------- fp32 -> (bf16 hi, bf16 lo) split (activations, K-major) ---
__global__ __launch_bounds__(256) void cvt_split(
    const float4* __restrict__ in,
    __nv_bfloat16* __restrict__ hi, __nv_bfloat16* __restrict__ lo, int n4)
{
    int i = blockIdx.x * 256 + threadIdx.x;
    if (i >= n4) return;
    float4 v = in[i];
    __nv_bfloat162 h01, h23, l01, l23;
    h01.x = __float2bfloat16(v.x);
    h01.y = __float2bfloat16(v.y);
    h23.x = __float2bfloat16(v.z);
    h23.y = __float2bfloat16(v.w);
    l01.x = __float2bfloat16(v.x - __bfloat162float(h01.x));
    l01.y = __float2bfloat16(v.y - __bfloat162float(h01.y));
    l23.x = __float2bfloat16(v.z - __bfloat162float(h23.x));
    l23.y = __float2bfloat16(v.w - __bfloat162float(h23.y));
    ((__nv_bfloat162*)&hi[4*i])[0] = h01;
    ((__nv_bfloat162*)&hi[4*i])[1] = h23;
    ((__nv_bfloat162*)&lo[4*i])[0] = l01;
    ((__nv_bfloat162*)&lo[4*i])[1] = l23;
}

// ---------------- weight split + transpose: W[K][N] -> Wt[N][K] hi/lo -------
__global__ __launch_bounds__(256) void cvt_wt(
    const float* __restrict__ Wq, const float* __restrict__ Wk,
    const float* __restrict__ Wv, const float* __restrict__ Wu,
    const float* __restrict__ Wo)
{
    __shared__ float ts[64 * 65];
    const int wsel = blockIdx.z;
    const float* W = (wsel == 0) ? Wq : (wsel == 1) ? Wk :
                     (wsel == 2) ? Wv : (wsel == 3) ? Wu : Wo;
    const int k0 = blockIdx.y * 64, n0 = blockIdx.x * 64;

    for (int i = threadIdx.x; i < 4096; i += 256) {
        int r = i >> 6, c = i & 63;
        ts[r * 65 + c] = W[(long)(k0 + r) * Dd + n0 + c];
    }
    __syncthreads();

    const long obase = (long)wsel * Dd * Dd;
    for (int task = threadIdx.x; task < 512; task += 256) {
        int j  = task >> 3;      // n within tile
        int g8 = task & 7;       // group of 8 k
        __nv_bfloat16 hi8[8], lo8[8];
#pragma unroll
        for (int e = 0; e < 8; e++) {
            float f = ts[(g8 * 8 + e) * 65 + j];
            __nv_bfloat16 h = __float2bfloat16(f);
            hi8[e] = h;
            lo8[e] = __float2bfloat16(f - __bfloat162float(h));
        }
        long o = obase + (long)(n0 + j) * Dd + k0 + g8 * 8;
        *(uint4*)&g_whi[o] = *(uint4*)hi8;
        *(uint4*)&g_wlo[o] = *(uint4*)lo8;
    }
}

// ---------------- GEMM: C[128x128 tile] = A @ Bt^T ---------------------------
// A: [M][K] K-major bf16 (hi/lo). Bt: [N][K] K-major bf16 (hi/lo). C fp32.
#define CHUNKS     16
#define TILE_BYTES 16384          // 128 rows x 128B
#define DYN_SMEM   (2*4*TILE_BYTES + 1024)

__device__ __forceinline__ void gemm_tc_body(
    const __nv_bfloat16* __restrict__ Ah, const __nv_bfloat16* __restrict__ Al,
    const __nv_bfloat16* __restrict__ Bh, const __nv_bfloat16* __restrict__ Bl,
    float* __restrict__ C, int brow, int bcol)
{
#if TC_OK
    // ---------------- tcgen05 path (arch-specific target only) -------------
    extern __shared__ __align__(16) char dynsm[];
    __shared__ __align__(8) uint64_t s_mbar[2];
    __shared__ uint32_t s_tmem[1];

    char* tiles_p = (char*)(((uintptr_t)dynsm + 1023) & ~(uintptr_t)1023);
    const uint32_t tiles_u = smem_u32(tiles_p);
    const int tid  = threadIdx.x;
    const int wid  = tid >> 5;
    const int lane = tid & 31;

    if (wid == 0)
        asm volatile("tcgen05.alloc.cta_group::1.sync.aligned.shared::cta.b32 [%0], %1;"
                     :: "r"(smem_u32(s_tmem)), "r"(128u) : "memory");
    if (tid == 0) {
        asm volatile("mbarrier.init.shared.b64 [%0], %1;"
                     :: "r"(smem_u32(&s_mbar[0])), "r"(1u) : "memory");
        asm volatile("mbarrier.init.shared.b64 [%0], %1;"
                     :: "r"(smem_u32(&s_mbar[1])), "r"(1u) : "memory");
    }
    __syncthreads();
    uint32_t tmem;
    asm volatile("ld.shared.b32 %0, [%1];" : "=r"(tmem) : "r"(smem_u32(s_tmem)));

    const uint64_t DESC_BASE =
        (2ull << 61) | (1ull << 46) | (64ull << 32) | (1ull << 16);

    int ph0 = 0, ph1 = 0;

    for (int c = 0; c < CHUNKS; c++) {
        const int buf = c & 1;
        char* pb = tiles_p + buf * (4 * TILE_BYTES);

        if (c >= 2) {
            mbar_wait(smem_u32(&s_mbar[buf]), buf ? ph1 : ph0);
            if (buf) ph1 ^= 1; else ph0 ^= 1;
        }

        const int k0 = c * 64;
        const __nv_bfloat16* s0 = Ah + (long)brow * Dd + k0;
        const __nv_bfloat16* s1 = Al + (long)brow * Dd + k0;
        const __nv_bfloat16* s2 = Bh + (long)bcol * Dd + k0;
        const __nv_bfloat16* s3 = Bl + (long)bcol * Dd + k0;

#pragma unroll
        for (int j = 0; j < 4; j++) {
            int idx = tid + j * 256;            // 0..1023 per operand
            int row = idx >> 3;
            int cb  = (idx & 7) << 4;           // byte offset in 128B row
            uint32_t so = SWZ(row * 128 + cb);
            int ce = cb >> 1;                   // element offset
            *(uint4*)(pb + 0 * TILE_BYTES + so) = *(const uint4*)(s0 + (long)row * Dd + ce);
            *(uint4*)(pb + 1 * TILE_BYTES + so) = *(const uint4*)(s1 + (long)row * Dd + ce);
            *(uint4*)(pb + 2 * TILE_BYTES + so) = *(const uint4*)(s2 + (long)row * Dd + ce);
            *(uint4*)(pb + 3 * TILE_BYTES + so) = *(const uint4*)(s3 + (long)row * Dd + ce);
        }
        asm volatile("fence.proxy.async.shared::cta;" ::: "memory");
        __syncthreads();

        if (tid == 0) {
            uint32_t tb = tiles_u + buf * (4 * TILE_BYTES);
            uint64_t adh = DESC_BASE | (uint64_t)(((tb + 0 * TILE_BYTES) >> 4) & 0x3FFF);
            uint64_t adl = DESC_BASE | (uint64_t)(((tb + 1 * TILE_BYTES) >> 4) & 0x3FFF);
            uint64_t bdh = DESC_BASE | (uint64_t)(((tb + 2 * TILE_BYTES) >> 4) & 0x3FFF);
            uint64_t bdl = DESC_BASE | (uint64_t)(((tb + 3 * TILE_BYTES) >> 4) & 0x3FFF);
#pragma unroll
            for (int k = 0; k < 4; k++) {
                uint32_t en0 = (c > 0 || k > 0) ? 1u : 0u;
                mma_f16_ss(tmem, adh + 2 * k, bdh + 2 * k, IDESC, en0);
                mma_f16_ss(tmem, adh + 2 * k, bdl + 2 * k, IDESC, 1u);
                mma_f16_ss(tmem, adl + 2 * k, bdh + 2 * k, IDESC, 1u);
            }
            asm volatile(
                "tcgen05.commit.cta_group::1.mbarrier::arrive::one.shared::cluster.b64 [%0];"
                :: "r"(smem_u32(&s_mbar[buf])) : "memory");
        }
    }

    mbar_wait(smem_u32(&s_mbar[0]), ph0);
    mbar_wait(smem_u32(&s_mbar[1]), ph1);
    asm volatile("tcgen05.fence::after_thread_sync;" ::: "memory");

    if (wid < 4) {
        int row = brow + wid * 32 + lane;
#pragma unroll
        for (int cb = 0; cb < 4; cb++) {
            uint32_t r[32];
            ldtm32(r, tmem + cb * 32);
            asm volatile("tcgen05.wait::ld.sync.aligned;" ::: "memory");
            float* crow = C + (long)row * Dd + bcol + cb * 32;
#pragma unroll
            for (int e = 0; e < 8; e++)
                *(float4*)(crow + 4 * e) = make_float4(
                    __uint_as_float(r[4*e+0]), __uint_as_float(r[4*e+1]),
                    __uint_as_float(r[4*e+2]), __uint_as_float(r[4*e+3]));
        }
    }
    __syncthreads();
    if (wid == 0)
        asm volatile("tcgen05.dealloc.cta_group::1.sync.aligned.b32 %0, %1;"
                     :: "r"(tmem), "r"(128u));
#else
    // ---------------- SIMT fallback (base-family target) -------------------
    // Round-5 sgemm structure; operands reconstructed from bf16 hi+lo.
    // Both A and Bt are K-major, so both transpose into smem identically.
    __shared__ __align__(16) float As[8][128];
    __shared__ __align__(16) float Bs[8][128];

    const int tid  = threadIdx.x;
    const int trow = (tid >> 4) << 2;   // 0,4,...,60
    const int tcol = (tid & 15) << 2;   // 0,4,...,60

    float acc[8][8];
#pragma unroll
    for (int i = 0; i < 8; i++)
#pragma unroll
        for (int j = 0; j < 8; j++) acc[i][j] = 0.f;

    const int  lrow = tid & 127;
    const bool isB  = tid >= 128;
    const __nv_bfloat16* hsrc = isB ? (Bh + (long)(bcol + lrow) * Dd)
                                    : (Ah + (long)(brow + lrow) * Dd);
    const __nv_bfloat16* lsrc = isB ? (Bl + (long)(bcol + lrow) * Dd)
                                    : (Al + (long)(brow + lrow) * Dd);

    for (int k0 = 0; k0 < Dd; k0 += 8) {
        __syncthreads();
        uint4 hraw = *(const uint4*)(hsrc + k0);
        uint4 lraw = *(const uint4*)(lsrc + k0);
        const __nv_bfloat16* h8 = (const __nv_bfloat16*)&hraw;
        const __nv_bfloat16* l8 = (const __nv_bfloat16*)&lraw;
        float (*dst)[128] = isB ? Bs : As;
#pragma unroll
        for (int e = 0; e < 8; e++)
            dst[e][lrow] = __bfloat162float(h8[e]) + __bfloat162float(l8[e]);
        __syncthreads();
#pragma unroll
        for (int kk = 0; kk < 8; kk++) {
            float4 a0 = *(const float4*)&As[kk][trow];
            float4 a1 = *(const float4*)&As[kk][64 + trow];
            float4 b0 = *(const float4*)&Bs[kk][tcol];
            float4 b1 = *(const float4*)&Bs[kk][64 + tcol];
            float ar[8] = {a0.x,a0.y,a0.z,a0.w, a1.x,a1.y,a1.z,a1.w};
            float br[8] = {b0.x,b0.y,b0.z,b0.w, b1.x,b1.y,b1.z,b1.w};
#pragma unroll
            for (int i = 0; i < 8; i++)
#pragma unroll
                for (int j = 0; j < 8; j++) acc[i][j] += ar[i] * br[j];
        }
    }

#pragma unroll
    for (int i = 0; i < 8; i++) {
        int r = brow + ((i < 4) ? (trow + i) : (64 + trow + i - 4));
        float4 c0 = make_float4(acc[i][0], acc[i][1], acc[i][2], acc[i][3]);
        float4 c1 = make_float4(acc[i][4], acc[i][5], acc[i][6], acc[i][7]);
        *(float4*)&C[(long)r * Dd + bcol + tcol]      = c0;
        *(float4*)&C[(long)r * Dd + bcol + 64 + tcol] = c1;
    }
#endif
}

__global__ __launch_bounds__(256) void proj4_tc()
{
    int z = blockIdx.z;
    const __nv_bfloat16* Bh = g_whi + (long)z * Dd * Dd;
    const __nv_bfloat16* Bl = g_wlo + (long)z * Dd * Dd;
    float* Cd = (z == 0) ? g_q : (z == 1) ? g_k : (z == 2) ? g_v : g_u;
    gemm_tc_body(g_xhi, g_xlo, Bh, Bl, Cd, blockIdx.y * 128, blockIdx.x * 128);
}

__global__ __launch_bounds__(256) void gemm_out_tc(float* __restrict__ out)
{
    gemm_tc_body(g_yhi, g_ylo, g_whi + 4l * Dd * Dd, g_wlo + 4l * Dd * Dd,
                 out, blockIdx.y * 128, blockIdx.x * 128);
}

// ---------------- per-segment sums ------------------------------------------
__global__ __launch_bounds__(256) void seg_sums()
{
    const int bx = blockIdx.x;
    const int s  = bx & (NSEG - 1);
    const int bh = bx >> 3;
    const int b  = bh >> 4;
    const int h  = bh & 15;
    const int tid = threadIdx.x;
    const int d  = tid >> 2;
    const int e0 = (tid & 3) << 4;

    __shared__ __align__(16) float Ks[32][64];
    __shared__ __align__(16) float Vs[32][64];

    float acc[16];
#pragma unroll
    for (int i = 0; i < 16; i++) acc[i] = 0.f;
    float ctx = 0.f;

    for (int tt = 0; tt < SEG; tt += 32) {
        __syncthreads();
        for (int i = tid; i < 512; i += 256) {
            int tok = i >> 4, c4 = (i & 15) << 2;
            long g = ((long)(b * Tt + s * SEG + tt + tok) * Hh + h) * DhD + c4;
            *(float4*)&Ks[tok][c4] = *(const float4*)&g_k[g];
            *(float4*)&Vs[tok][c4] = *(const float4*)&g_v[g];
        }
        __syncthreads();
#pragma unroll
        for (int j = 0; j < 32; j++) {
            float kd = Ks[j][d];
            ctx += kd;
            const float4* vr = (const float4*)&Vs[j][e0];
#pragma unroll
            for (int q4 = 0; q4 < 4; q4++) {
                float4 vv = vr[q4];
                acc[4*q4+0] += kd * vv.x;
                acc[4*q4+1] += kd * vv.y;
                acc[4*q4+2] += kd * vv.z;
                acc[4*q4+3] += kd * vv.w;
            }
        }
    }
    long base = ((long)(bh * NSEG + s) * DhD + d) * DhD + e0;
#pragma unroll
    for (int q4 = 0; q4 < 4; q4++)
        *(float4*)&g_Sseg[base + 4*q4] =
            make_float4(acc[4*q4], acc[4*q4+1], acc[4*q4+2], acc[4*q4+3]);
    if ((tid & 3) == 0) g_cctx[(bh * NSEG + s) * DhD + d] = ctx;
}

// ---------------- prefix over segments --------------------------------------
__global__ __launch_bounds__(256) void seg_prefix()
{
    const int bh = blockIdx.x;
    for (int i = threadIdx.x; i < DhD * DhD; i += 256) {
        float run = 0.f;
#pragma unroll
        for (int s = 0; s < NSEG; s++) {
            long idx = ((long)(bh * NSEG + s)) * (DhD * DhD) + i;
            run += g_Sseg[idx];
            g_cS[idx] = run;
        }
    }
}

// ---------------- attention/mixing ------------------------------------------
__global__ __launch_bounds__(256) void attn_kernel()
{
    const int bx  = blockIdx.x;
    const int seg = bx & (NSEG - 1);
    const int bh  = bx >> 3;
    const int b   = bh >> 4;
    const int h   = bh & 15;
    const int t   = threadIdx.x;
    const int tg  = seg * SEG + t;
    const int cur = seg;

    __shared__ __align__(16) float Ks[64][64];
    __shared__ __align__(16) float Vs[64][64];
    __shared__ __align__(16) float Cs[8][64];
    __shared__ float Wsm[8][256];

    const long rowbase = ((long)(b * Tt + tg) * Hh + h) * DhD;

    float sc[8];
    float ons = 0.f;
    {
        float ureg[64];
        const float4* up = (const float4*)&g_u[rowbase];
#pragma unroll
        for (int i = 0; i < 16; i++) {
            float4 w4 = up[i];
            ureg[4*i] = w4.x; ureg[4*i+1] = w4.y; ureg[4*i+2] = w4.z; ureg[4*i+3] = w4.w;
        }
        for (int i = t; i < cur * 64; i += 256)
            Cs[i >> 6][i & 63] = g_cctx[(bh * NSEG + (i >> 6)) * DhD + (i & 63)];
        __syncthreads();
#pragma unroll
        for (int s = 0; s < 8; s++) {
            float a = 0.f;
            if (s < cur) {
                const float4* cp = (const float4*)Cs[s];
#pragma unroll
                for (int j = 0; j < 16; j++) {
                    float4 c4 = cp[j];
                    a += ureg[4*j]*c4.x + ureg[4*j+1]*c4.y + ureg[4*j+2]*c4.z + ureg[4*j+3]*c4.w;
                }
            }
            sc[s] = a;
        }
        for (int tile = 0; tile < 4; tile++) {
            __syncthreads();
            for (int i = t; i < 1024; i += 256) {
                int tok = i >> 4, c4 = (i & 15) << 2;
                long g = ((long)(b * Tt + seg * SEG + tile * 64 + tok) * Hh + h) * DhD + c4;
                *(float4*)&Ks[tok][c4] = *(const float4*)&g_k[g];
            }
            __syncthreads();
            int lim = t - tile * 64;
            if (lim >= 0) {
                int n = lim < 63 ? lim : 63;
                for (int tp = 0; tp <= n; tp++) {
                    const float4* kr = (const float4*)Ks[tp];
                    float a = 0.f;
#pragma unroll
                    for (int j = 0; j < 16; j++) {
                        float4 k4 = kr[j];
                        a += ureg[4*j]*k4.x + ureg[4*j+1]*k4.y + ureg[4*j+2]*k4.z + ureg[4*j+3]*k4.w;
                    }
                    ons += a;
                }
            }
        }
    }

    float wcur;
    if (cur == 0) {
        wcur = 1.f;
    } else {
        float m = ons;
#pragma unroll
        for (int s = 0; s < 8; s++) if (s < cur && sc[s] > m) m = sc[s];
        float eon = expf(ons - m);
        float denom = eon;
#pragma unroll
        for (int s = 0; s < 8; s++) {
            if (s < cur) { float e = expf(sc[s] - m); sc[s] = e; denom += e; }
        }
        float inv = 1.f / denom;
        wcur = eon * inv;
#pragma unroll
        for (int s = 0; s < 8; s++)
            if (s < cur) Wsm[s][t] = sc[s] * inv + ((s == cur - 1) ? wcur : 0.f);
    }

    float4 q4r[16];
    {
        const float4* qp = (const float4*)&g_q[rowbase];
#pragma unroll
        for (int i = 0; i < 16; i++) q4r[i] = qp[i];
    }
    float outr[64];
#pragma unroll
    for (int i = 0; i < 64; i++) outr[i] = 0.f;

    for (int s = 0; s < cur; s++) {
        __syncthreads();
        for (int i = t; i < 1024; i += 256) {
            int dd = i >> 4, c4 = (i & 15) << 2;
            *(float4*)&Ks[dd][c4] =
                *(const float4*)&g_cS[((long)(bh * NSEG + s)) * (DhD*DhD) + dd * 64 + c4];
        }
        __syncthreads();
        float ws = Wsm[s][t];
#pragma unroll
        for (int d4 = 0; d4 < 16; d4++) {
            float4 qv = q4r[d4];
            float fq[4] = {ws*qv.x, ws*qv.y, ws*qv.z, ws*qv.w};
#pragma unroll
            for (int c = 0; c < 4; c++) {
                float f = fq[c];
                const float4* sr = (const float4*)Ks[4*d4 + c];
#pragma unroll
                for (int e = 0; e < 16; e++) {
                    float4 s4 = sr[e];
                    outr[4*e+0] += f * s4.x;
                    outr[4*e+1] += f * s4.y;
                    outr[4*e+2] += f * s4.z;
                    outr[4*e+3] += f * s4.w;
                }
            }
        }
    }

    for (int tile = 0; tile < 4; tile++) {
        __syncthreads();
        for (int i = t; i < 1024; i += 256) {
            int tok = i >> 4, c4 = (i & 15) << 2;
            long g = ((long)(b * Tt + seg * SEG + tile * 64 + tok) * Hh + h) * DhD + c4;
            *(float4*)&Ks[tok][c4] = *(const float4*)&g_k[g];
            *(float4*)&Vs[tok][c4] = *(const float4*)&g_v[g];
        }
        __syncthreads();
        int lim = t - tile * 64;
        if (lim >= 0) {
            int n = lim < 63 ? lim : 63;
            for (int tp = 0; tp <= n; tp++) {
                const float4* kr = (const float4*)Ks[tp];
                float a = 0.f;
#pragma unroll
                for (int j = 0; j < 16; j++) {
                    float4 k4 = kr[j];
                    a += q4r[j].x*k4.x + q4r[j].y*k4.y + q4r[j].z*k4.z + q4r[j].w*k4.w;
                }
                float f = wcur * a;
                const float4* vr = (const float4*)Vs[tp];
#pragma unroll
                for (int e = 0; e < 16; e++) {
                    float4 v4 = vr[e];
                    outr[4*e+0] += f * v4.x;
                    outr[4*e+1] += f * v4.y;
                    outr[4*e+2] += f * v4.z;
                    outr[4*e+3] += f * v4.w;
                }
            }
        }
    }

    float4* yp = (float4*)&g_y[rowbase];
#pragma unroll
    for (int e = 0; e < 16; e++)
        yp[e] = make_float4(outr[4*e], outr[4*e+1], outr[4*e+2], outr[4*e+3]);
}

// ---------------- launch ----------------------------------------------------
extern "C" void kernel_launch(void* const* d_in, const int* in_sizes, int n_in,
                              void* d_out, int out_size)
{
    const float* x  = (const float*)d_in[0];
    const float* Wq = (const float*)d_in[1];
    const float* Wk = (const float*)d_in[2];
    const float* Wv = (const float*)d_in[3];
    const float* Wu = (const float*)d_in[4];
    const float* Wo = (const float*)d_in[5];
    float* out = (float*)d_out;

    __nv_bfloat16 *pxh, *pxl, *pyh, *pyl;
    float* pyf;
    cudaGetSymbolAddress((void**)&pxh, g_xhi);
    cudaGetSymbolAddress((void**)&pxl, g_xlo);
    cudaGetSymbolAddress((void**)&pyh, g_yhi);
    cudaGetSymbolAddress((void**)&pyl, g_ylo);
    cudaGetSymbolAddress((void**)&pyf, g_y);

    cudaFuncSetAttribute(proj4_tc,    cudaFuncAttributeMaxDynamicSharedMemorySize, DYN_SMEM);
    cudaFuncSetAttribute(gemm_out_tc, cudaFuncAttributeMaxDynamicSharedMemorySize, DYN_SMEM);

    const int N4 = BT * Dd / 4;
    cvt_split<<<N4 / 256, 256>>>((const float4*)x, pxh, pxl, N4);

    dim3 gw(16, 16, 5);
    cvt_wt<<<gw, 256>>>(Wq, Wk, Wv, Wu, Wo);

    dim3 gp(Dd / 128, BT / 128, 4);                // (8, 64, 4)
    proj4_tc<<<gp, 256, DYN_SMEM>>>();

    seg_sums  <<<BH * NSEG, 256>>>();
    seg_prefix<<<BH,        256>>>();
    attn_kernel<<<BH * NSEG, 256>>>();

    cvt_split<<<N4 / 256, 256>>>((const float4*)pyf, pyh, pyl, N4);

    dim3 gg(Dd / 128, BT / 128);                   // (8, 64)
    gemm_out_tc<<<gg, 256, DYN_SMEM>>>(out);
}

// round 14
// speedup vs baseline: 2.1352x; 1.6054x over previous
#include <cuda_runtime.h>
#include <cuda_bf16.h>
#include <math.h>
#include <stdint.h>

#define Bb   4
#define Tt   2048
#define Dd   1024
#define Hh   16
#define DhD  64
#define SEG  256
#define NSEG 8
#define BT   (Bb*Tt)      // 8192
#define BH   (Bb*Hh)      // 64

#define SWZ(o) ((o) ^ ((((o) >> 3)) & 0x70))

// idesc kind::f16 cg1: F32 accum, BF16 a/b, N=128, M=128
#define IDESC 0x8200490u

// tcgen05 is only available on arch-SPECIFIC targets (sm_103a / sm_100a).
#if defined(__CUDA_ARCH_FEAT_SM103_ALL) || defined(__CUDA_ARCH_FEAT_SM100_ALL) || defined(__CUDA_ARCH_SPECIFIC__)
#define TC_OK 1
#else
#define TC_OK 0
#endif

// ---------------- scratch (device globals; no allocations allowed) ----------
__device__ __align__(16) float g_q[BT*Dd];
__device__ __align__(16) float g_k[BT*Dd];
__device__ __align__(16) float g_v[BT*Dd];
__device__ __align__(16) float g_u[BT*Dd];
__device__ __align__(16) float g_y[BT*Dd];
__device__ __align__(16) float g_Sseg[BH*NSEG*DhD*DhD];
__device__ __align__(16) float g_cS  [BH*NSEG*DhD*DhD];
__device__ __align__(16) float g_cctx[BH*NSEG*DhD];

// bf16 split operands (weights stored TRANSPOSED: [N][K] K-major)
__device__ __align__(16) __nv_bfloat16 g_xhi[BT*Dd];
__device__ __align__(16) __nv_bfloat16 g_xlo[BT*Dd];
__device__ __align__(16) __nv_bfloat16 g_yhi[BT*Dd];
__device__ __align__(16) __nv_bfloat16 g_ylo[BT*Dd];
__device__ __align__(16) __nv_bfloat16 g_whi[5*Dd*Dd];
__device__ __align__(16) __nv_bfloat16 g_wlo[5*Dd*Dd];

// ---------------- small helpers ---------------------------------------------
__device__ __forceinline__ uint32_t smem_u32(const void* p) {
    uint32_t a;
    asm("{ .reg .u64 t; cvta.to.shared.u64 t, %1; cvt.u32.u64 %0, t; }"
        : "=r"(a) : "l"(p));
    return a;
}

#if TC_OK
__device__ __forceinline__ void mma_f16_ss(uint32_t d, uint64_t ad, uint64_t bd,
                                           uint32_t idesc, uint32_t en) {
    asm volatile(
        "{\n\t.reg .pred p;\n\tsetp.ne.u32 p, %5, 0;\n\t"
        "tcgen05.mma.cta_group::1.kind::f16 [%0], %1, %2, %3, {%4,%4,%4,%4}, p;\n\t}"
        :: "r"(d), "l"(ad), "l"(bd), "r"(idesc), "r"(0u), "r"(en) : "memory");
}

__device__ __forceinline__ void mbar_wait(uint32_t mbar, int parity) {
    asm volatile(
        "{\n\t.reg .pred P;\n\t"
        "LAB_%=:\n\t"
        "mbarrier.try_wait.parity.acquire.cta.shared::cta.b64 P, [%0], %1;\n\t"
        "@!P bra LAB_%=;\n\t}"
        :: "r"(mbar), "r"(parity) : "memory");
}

__device__ __forceinline__ void ldtm32(uint32_t* r, uint32_t addr) {
    asm volatile(
        "tcgen05.ld.sync.aligned.32x32b.x32.b32 "
        "{%0, %1, %2, %3, %4, %5, %6, %7, "
        " %8, %9, %10, %11, %12, %13, %14, %15, "
        " %16, %17, %18, %19, %20, %21, %22, %23, "
        " %24, %25, %26, %27, %28, %29, %30, %31}, [%32];"
        : "=r"(r[0]),  "=r"(r[1]),  "=r"(r[2]),  "=r"(r[3]),
          "=r"(r[4]),  "=r"(r[5]),  "=r"(r[6]),  "=r"(r[7]),
          "=r"(r[8]),  "=r"(r[9]),  "=r"(r[10]), "=r"(r[11]),
          "=r"(r[12]), "=r"(r[13]), "=r"(r[14]), "=r"(r[15]),
          "=r"(r[16]), "=r"(r[17]), "=r"(r[18]), "=r"(r[19]),
          "=r"(r[20]), "=r"(r[21]), "=r"(r[22]), "=r"(r[23]),
          "=r"(r[24]), "=r"(r[25]), "=r"(r[26]), "=r"(r[27]),
          "=r"(r[28]), "=r"(r[29]), "=r"(r[30]), "=r"(r[31])
        : "r"(addr));
}

__device__ __forceinline__ void cp16(uint32_t saddr, const void* gptr) {
    asm volatile("cp.async.cg.shared.global [%0], [%1], 16;"
                 :: "r"(saddr), "l"(gptr));
}
#endif

// ---------------- fp32 -> (bf16 hi, bf16 lo) split (activations, K-major) ---
__global__ __launch_bounds__(256) void cvt_split(
    const float4* __restrict__ in,
    __nv_bfloat16* __restrict__ hi, __nv_bfloat16* __restrict__ lo, int n4)
{
    int i = blockIdx.x * 256 + threadIdx.x;
    if (i >= n4) return;
    float4 v = in[i];
    __nv_bfloat162 h01, h23, l01, l23;
    h01.x = __float2bfloat16(v.x);
    h01.y = __float2bfloat16(v.y);
    h23.x = __float2bfloat16(v.z);
    h23.y = __float2bfloat16(v.w);
    l01.x = __float2bfloat16(v.x - __bfloat162float(h01.x));
    l01.y = __float2bfloat16(v.y - __bfloat162float(h01.y));
    l23.x = __float2bfloat16(v.z - __bfloat162float(h23.x));
    l23.y = __float2bfloat16(v.w - __bfloat162float(h23.y));
    ((__nv_bfloat162*)&hi[4*i])[0] = h01;
    ((__nv_bfloat162*)&hi[4*i])[1] = h23;
    ((__nv_bfloat162*)&lo[4*i])[0] = l01;
    ((__nv_bfloat162*)&lo[4*i])[1] = l23;
}

// ---------------- weight split + transpose: W[K][N] -> Wt[N][K] hi/lo -------
__global__ __launch_bounds__(256) void cvt_wt(
    const float* __restrict__ Wq, const float* __restrict__ Wk,
    const float* __restrict__ Wv, const float* __restrict__ Wu,
    const float* __restrict__ Wo)
{
    __shared__ float ts[64 * 65];
    const int wsel = blockIdx.z;
    const float* W = (wsel == 0) ? Wq : (wsel == 1) ? Wk :
                     (wsel == 2) ? Wv : (wsel == 3) ? Wu : Wo;
    const int k0 = blockIdx.y * 64, n0 = blockIdx.x * 64;

    for (int i = threadIdx.x; i < 4096; i += 256) {
        int r = i >> 6, c = i & 63;
        ts[r * 65 + c] = W[(long)(k0 + r) * Dd + n0 + c];
    }
    __syncthreads();

    const long obase = (long)wsel * Dd * Dd;
    for (int task = threadIdx.x; task < 512; task += 256) {
        int j  = task >> 3;
        int g8 = task & 7;
        __nv_bfloat16 hi8[8], lo8[8];
#pragma unroll
        for (int e = 0; e < 8; e++) {
            float f = ts[(g8 * 8 + e) * 65 + j];
            __nv_bfloat16 h = __float2bfloat16(f);
            hi8[e] = h;
            lo8[e] = __float2bfloat16(f - __bfloat162float(h));
        }
        long o = obase + (long)(n0 + j) * Dd + k0 + g8 * 8;
        *(uint4*)&g_whi[o] = *(uint4*)hi8;
        *(uint4*)&g_wlo[o] = *(uint4*)lo8;
    }
}

// ---------------- GEMM: C[128x128 tile] = A @ Bt^T ---------------------------
// A: [M][K] K-major bf16 (hi/lo). Bt: [N][K] K-major bf16 (hi/lo). C fp32.
#define CHUNKS     16
#define STAGES     3
#define TILE_BYTES 16384          // 128 rows x 128B
#define STAGE_BYTES (4*TILE_BYTES)
#define DYN_SMEM   (STAGES*STAGE_BYTES + 1024)

__device__ __forceinline__ void gemm_tc_body(
    const __nv_bfloat16* __restrict__ Ah, const __nv_bfloat16* __restrict__ Al,
    const __nv_bfloat16* __restrict__ Bh, const __nv_bfloat16* __restrict__ Bl,
    float* __restrict__ C, int brow, int bcol)
{
#if TC_OK
    // ---------------- tcgen05 path with cp.async 3-stage pipeline ----------
    extern __shared__ __align__(16) char dynsm[];
    __shared__ __align__(8) uint64_t s_mbar[STAGES];
    __shared__ uint32_t s_tmem[1];

    char* tiles_p = (char*)(((uintptr_t)dynsm + 1023) & ~(uintptr_t)1023);
    const uint32_t tiles_u = smem_u32(tiles_p);
    const int tid  = threadIdx.x;
    const int wid  = tid >> 5;
    const int lane = tid & 31;

    if (wid == 0)
        asm volatile("tcgen05.alloc.cta_group::1.sync.aligned.shared::cta.b32 [%0], %1;"
                     :: "r"(smem_u32(s_tmem)), "r"(128u) : "memory");
    if (tid == 0) {
#pragma unroll
        for (int b = 0; b < STAGES; b++)
            asm volatile("mbarrier.init.shared.b64 [%0], %1;"
                         :: "r"(smem_u32(&s_mbar[b])), "r"(1u) : "memory");
    }
    __syncthreads();
    uint32_t tmem;
    asm volatile("ld.shared.b32 %0, [%1];" : "=r"(tmem) : "r"(smem_u32(s_tmem)));

    const uint64_t DESC_BASE =
        (2ull << 61) | (1ull << 46) | (64ull << 32) | (1ull << 16);

    // per-thread load addressing (constant across chunks)
    const int l_row = tid >> 1;                 // 0..127
    const int l_cb0 = (tid & 1) << 5;           // 0 or 32: two 16B slots each
    int ph[STAGES];
#pragma unroll
    for (int b = 0; b < STAGES; b++) ph[b] = 0;

    // issue async loads for chunk c into its stage buffer (16 cp.async/thread)
    auto issue_load = [&](int c) {
        const uint32_t pu = tiles_u + (c % STAGES) * STAGE_BYTES;
        const int k0 = c * 64;
        const __nv_bfloat16* s0 = Ah + (long)(brow + l_row) * Dd + k0;
        const __nv_bfloat16* s1 = Al + (long)(brow + l_row) * Dd + k0;
        const __nv_bfloat16* s2 = Bh + (long)(bcol + l_row) * Dd + k0;
        const __nv_bfloat16* s3 = Bl + (long)(bcol + l_row) * Dd + k0;
#pragma unroll
        for (int j = 0; j < 4; j++) {
            int cb = l_cb0 + ((j & 1) << 4) + ((j >> 1) << 6); // 0,16,64,80 (+l_cb0)
            uint32_t so = SWZ(l_row * 128 + cb);
            int ce = cb >> 1;
            cp16(pu + 0 * TILE_BYTES + so, s0 + ce);
            cp16(pu + 1 * TILE_BYTES + so, s1 + ce);
            cp16(pu + 2 * TILE_BYTES + so, s2 + ce);
            cp16(pu + 3 * TILE_BYTES + so, s3 + ce);
        }
        asm volatile("cp.async.commit_group;" ::: "memory");
    };

#pragma unroll
    for (int p = 0; p < STAGES; p++) issue_load(p);

    for (int c = 0; c < CHUNKS; c++) {
        const int buf = c % STAGES;
        // chunk c's group complete (keep STAGES-1 most recent pending)
        asm volatile("cp.async.wait_group %0;" :: "n"(STAGES - 1) : "memory");
        asm volatile("fence.proxy.async.shared::cta;" ::: "memory");
        __syncthreads();

        if (tid == 0) {
            uint32_t tb = tiles_u + buf * STAGE_BYTES;
            uint64_t adh = DESC_BASE | (uint64_t)(((tb + 0 * TILE_BYTES) >> 4) & 0x3FFF);
            uint64_t adl = DESC_BASE | (uint64_t)(((tb + 1 * TILE_BYTES) >> 4) & 0x3FFF);
            uint64_t bdh = DESC_BASE | (uint64_t)(((tb + 2 * TILE_BYTES) >> 4) & 0x3FFF);
            uint64_t bdl = DESC_BASE | (uint64_t)(((tb + 3 * TILE_BYTES) >> 4) & 0x3FFF);
#pragma unroll
            for (int k = 0; k < 4; k++) {
                uint32_t en0 = (c > 0 || k > 0) ? 1u : 0u;
                mma_f16_ss(tmem, adh + 2 * k, bdh + 2 * k, IDESC, en0);
                mma_f16_ss(tmem, adh + 2 * k, bdl + 2 * k, IDESC, 1u);
                mma_f16_ss(tmem, adl + 2 * k, bdh + 2 * k, IDESC, 1u);
            }
            asm volatile(
                "tcgen05.commit.cta_group::1.mbarrier::arrive::one.shared::cluster.b64 [%0];"
                :: "r"(smem_u32(&s_mbar[buf])) : "memory");
        }

        // MMA(c) must finish before this buffer is reloaded
        mbar_wait(smem_u32(&s_mbar[buf]), ph[buf]);
        ph[buf] ^= 1;

        if (c + STAGES < CHUNKS)
            issue_load(c + STAGES);
        else
            asm volatile("cp.async.commit_group;" ::: "memory"); // keep group count
    }

    asm volatile("tcgen05.fence::after_thread_sync;" ::: "memory");

    if (wid < 4) {
        int row = brow + wid * 32 + lane;
#pragma unroll
        for (int cb = 0; cb < 4; cb++) {
            uint32_t r[32];
            ldtm32(r, tmem + cb * 32);
            asm volatile("tcgen05.wait::ld.sync.aligned;" ::: "memory");
            float* crow = C + (long)row * Dd + bcol + cb * 32;
#pragma unroll
            for (int e = 0; e < 8; e++)
                *(float4*)(crow + 4 * e) = make_float4(
                    __uint_as_float(r[4*e+0]), __uint_as_float(r[4*e+1]),
                    __uint_as_float(r[4*e+2]), __uint_as_float(r[4*e+3]));
        }
    }
    __syncthreads();
    if (wid == 0)
        asm volatile("tcgen05.dealloc.cta_group::1.sync.aligned.b32 %0, %1;"
                     :: "r"(tmem), "r"(128u));
#else
    // ---------------- SIMT fallback (base-family target) -------------------
    __shared__ __align__(16) float As[8][128];
    __shared__ __align__(16) float Bs[8][128];

    const int tid  = threadIdx.x;
    const int trow = (tid >> 4) << 2;
    const int tcol = (tid & 15) << 2;

    float acc[8][8];
#pragma unroll
    for (int i = 0; i < 8; i++)
#pragma unroll
        for (int j = 0; j < 8; j++) acc[i][j] = 0.f;

    const int  lrow = tid & 127;
    const bool isB  = tid >= 128;
    const __nv_bfloat16* hsrc = isB ? (Bh + (long)(bcol + lrow) * Dd)
                                    : (Ah + (long)(brow + lrow) * Dd);
    const __nv_bfloat16* lsrc = isB ? (Bl + (long)(bcol + lrow) * Dd)
                                    : (Al + (long)(brow + lrow) * Dd);

    for (int k0 = 0; k0 < Dd; k0 += 8) {
        __syncthreads();
        uint4 hraw = *(const uint4*)(hsrc + k0);
        uint4 lraw = *(const uint4*)(lsrc + k0);
        const __nv_bfloat16* h8 = (const __nv_bfloat16*)&hraw;
        const __nv_bfloat16* l8 = (const __nv_bfloat16*)&lraw;
        float (*dst)[128] = isB ? Bs : As;
#pragma unroll
        for (int e = 0; e < 8; e++)
            dst[e][lrow] = __bfloat162float(h8[e]) + __bfloat162float(l8[e]);
        __syncthreads();
#pragma unroll
        for (int kk = 0; kk < 8; kk++) {
            float4 a0 = *(const float4*)&As[kk][trow];
            float4 a1 = *(const float4*)&As[kk][64 + trow];
            float4 b0 = *(const float4*)&Bs[kk][tcol];
            float4 b1 = *(const float4*)&Bs[kk][64 + tcol];
            float ar[8] = {a0.x,a0.y,a0.z,a0.w, a1.x,a1.y,a1.z,a1.w};
            float br[8] = {b0.x,b0.y,b0.z,b0.w, b1.x,b1.y,b1.z,b1.w};
#pragma unroll
            for (int i = 0; i < 8; i++)
#pragma unroll
                for (int j = 0; j < 8; j++) acc[i][j] += ar[i] * br[j];
        }
    }

#pragma unroll
    for (int i = 0; i < 8; i++) {
        int r = brow + ((i < 4) ? (trow + i) : (64 + trow + i - 4));
        float4 c0 = make_float4(acc[i][0], acc[i][1], acc[i][2], acc[i][3]);
        float4 c1 = make_float4(acc[i][4], acc[i][5], acc[i][6], acc[i][7]);
        *(float4*)&C[(long)r * Dd + bcol + tcol]      = c0;
        *(float4*)&C[(long)r * Dd + bcol + 64 + tcol] = c1;
    }
#endif
}

__global__ __launch_bounds__(256) void proj4_tc()
{
    int z = blockIdx.z;
    const __nv_bfloat16* Bh = g_whi + (long)z * Dd * Dd;
    const __nv_bfloat16* Bl = g_wlo + (long)z * Dd * Dd;
    float* Cd = (z == 0) ? g_q : (z == 1) ? g_k : (z == 2) ? g_v : g_u;
    gemm_tc_body(g_xhi, g_xlo, Bh, Bl, Cd, blockIdx.y * 128, blockIdx.x * 128);
}

__global__ __launch_bounds__(256) void gemm_out_tc(float* __restrict__ out)
{
    gemm_tc_body(g_yhi, g_ylo, g_whi + 4l * Dd * Dd, g_wlo + 4l * Dd * Dd,
                 out, blockIdx.y * 128, blockIdx.x * 128);
}

// ---------------- per-segment sums ------------------------------------------
__global__ __launch_bounds__(256) void seg_sums()
{
    const int bx = blockIdx.x;
    const int s  = bx & (NSEG - 1);
    const int bh = bx >> 3;
    const int b  = bh >> 4;
    const int h  = bh & 15;
    const int tid = threadIdx.x;
    const int d  = tid >> 2;
    const int e0 = (tid & 3) << 4;

    __shared__ __align__(16) float Ks[32][64];
    __shared__ __align__(16) float Vs[32][64];

    float acc[16];
#pragma unroll
    for (int i = 0; i < 16; i++) acc[i] = 0.f;
    float ctx = 0.f;

    for (int tt = 0; tt < SEG; tt += 32) {
        __syncthreads();
        for (int i = tid; i < 512; i += 256) {
            int tok = i >> 4, c4 = (i & 15) << 2;
            long g = ((long)(b * Tt + s * SEG + tt + tok) * Hh + h) * DhD + c4;
            *(float4*)&Ks[tok][c4] = *(const float4*)&g_k[g];
            *(float4*)&Vs[tok][c4] = *(const float4*)&g_v[g];
        }
        __syncthreads();
#pragma unroll
        for (int j = 0; j < 32; j++) {
            float kd = Ks[j][d];
            ctx += kd;
            const float4* vr = (const float4*)&Vs[j][e0];
#pragma unroll
            for (int q4 = 0; q4 < 4; q4++) {
                float4 vv = vr[q4];
                acc[4*q4+0] += kd * vv.x;
                acc[4*q4+1] += kd * vv.y;
                acc[4*q4+2] += kd * vv.z;
                acc[4*q4+3] += kd * vv.w;
            }
        }
    }
    long base = ((long)(bh * NSEG + s) * DhD + d) * DhD + e0;
#pragma unroll
    for (int q4 = 0; q4 < 4; q4++)
        *(float4*)&g_Sseg[base + 4*q4] =
            make_float4(acc[4*q4], acc[4*q4+1], acc[4*q4+2], acc[4*q4+3]);
    if ((tid & 3) == 0) g_cctx[(bh * NSEG + s) * DhD + d] = ctx;
}

// ---------------- prefix over segments --------------------------------------
__global__ __launch_bounds__(256) void seg_prefix()
{
    const int bh = blockIdx.x;
    for (int i = threadIdx.x; i < DhD * DhD; i += 256) {
        float run = 0.f;
#pragma unroll
        for (int s = 0; s < NSEG; s++) {
            long idx = ((long)(bh * NSEG + s)) * (DhD * DhD) + i;
            run += g_Sseg[idx];
            g_cS[idx] = run;
        }
    }
}

// ---------------- attention/mixing ------------------------------------------
__global__ __launch_bounds__(256) void attn_kernel()
{
    const int bx  = blockIdx.x;
    const int seg = bx & (NSEG - 1);
    const int bh  = bx >> 3;
    const int b   = bh >> 4;
    const int h   = bh & 15;
    const int t   = threadIdx.x;
    const int tg  = seg * SEG + t;
    const int cur = seg;

    __shared__ __align__(16) float Ks[64][64];
    __shared__ __align__(16) float Vs[64][64];
    __shared__ __align__(16) float Cs[8][64];
    __shared__ float Wsm[8][256];

    const long rowbase = ((long)(b * Tt + tg) * Hh + h) * DhD;

    float sc[8];
    float ons = 0.f;
    {
        float ureg[64];
        const float4* up = (const float4*)&g_u[rowbase];
#pragma unroll
        for (int i = 0; i < 16; i++) {
            float4 w4 = up[i];
            ureg[4*i] = w4.x; ureg[4*i+1] = w4.y; ureg[4*i+2] = w4.z; ureg[4*i+3] = w4.w;
        }
        for (int i = t; i < cur * 64; i += 256)
            Cs[i >> 6][i & 63] = g_cctx[(bh * NSEG + (i >> 6)) * DhD + (i & 63)];
        __syncthreads();
#pragma unroll
        for (int s = 0; s < 8; s++) {
            float a = 0.f;
            if (s < cur) {
                const float4* cp = (const float4*)Cs[s];
#pragma unroll
                for (int j = 0; j < 16; j++) {
                    float4 c4 = cp[j];
                    a += ureg[4*j]*c4.x + ureg[4*j+1]*c4.y + ureg[4*j+2]*c4.z + ureg[4*j+3]*c4.w;
                }
            }
            sc[s] = a;
        }
        for (int tile = 0; tile < 4; tile++) {
            __syncthreads();
            for (int i = t; i < 1024; i += 256) {
                int tok = i >> 4, c4 = (i & 15) << 2;
                long g = ((long)(b * Tt + seg * SEG + tile * 64 + tok) * Hh + h) * DhD + c4;
                *(float4*)&Ks[tok][c4] = *(const float4*)&g_k[g];
            }
            __syncthreads();
            int lim = t - tile * 64;
            if (lim >= 0) {
                int n = lim < 63 ? lim : 63;
                for (int tp = 0; tp <= n; tp++) {
                    const float4* kr = (const float4*)Ks[tp];
                    float a = 0.f;
#pragma unroll
                    for (int j = 0; j < 16; j++) {
                        float4 k4 = kr[j];
                        a += ureg[4*j]*k4.x + ureg[4*j+1]*k4.y + ureg[4*j+2]*k4.z + ureg[4*j+3]*k4.w;
                    }
                    ons += a;
                }
            }
        }
    }

    float wcur;
    if (cur == 0) {
        wcur = 1.f;
    } else {
        float m = ons;
#pragma unroll
        for (int s = 0; s < 8; s++) if (s < cur && sc[s] > m) m = sc[s];
        float eon = expf(ons - m);
        float denom = eon;
#pragma unroll
        for (int s = 0; s < 8; s++) {
            if (s < cur) { float e = expf(sc[s] - m); sc[s] = e; denom += e; }
        }
        float inv = 1.f / denom;
        wcur = eon * inv;
#pragma unroll
        for (int s = 0; s < 8; s++)
            if (s < cur) Wsm[s][t] = sc[s] * inv + ((s == cur - 1) ? wcur : 0.f);
    }

    float4 q4r[16];
    {
        const float4* qp = (const float4*)&g_q[rowbase];
#pragma unroll
        for (int i = 0; i < 16; i++) q4r[i] = qp[i];
    }
    float outr[64];
#pragma unroll
    for (int i = 0; i < 64; i++) outr[i] = 0.f;

    for (int s = 0; s < cur; s++) {
        __syncthreads();
        for (int i = t; i < 1024; i += 256) {
            int dd = i >> 4, c4 = (i & 15) << 2;
            *(float4*)&Ks[dd][c4] =
                *(const float4*)&g_cS[((long)(bh * NSEG + s)) * (DhD*DhD) + dd * 64 + c4];
        }
        __syncthreads();
        float ws = Wsm[s][t];
#pragma unroll
        for (int d4 = 0; d4 < 16; d4++) {
            float4 qv = q4r[d4];
            float fq[4] = {ws*qv.x, ws*qv.y, ws*qv.z, ws*qv.w};
#pragma unroll
            for (int c = 0; c < 4; c++) {
                float f = fq[c];
                const float4* sr = (const float4*)Ks[4*d4 + c];
#pragma unroll
                for (int e = 0; e < 16; e++) {
                    float4 s4 = sr[e];
                    outr[4*e+0] += f * s4.x;
                    outr[4*e+1] += f * s4.y;
                    outr[4*e+2] += f * s4.z;
                    outr[4*e+3] += f * s4.w;
                }
            }
        }
    }

    for (int tile = 0; tile < 4; tile++) {
        __syncthreads();
        for (int i = t; i < 1024; i += 256) {
            int tok = i >> 4, c4 = (i & 15) << 2;
            long g = ((long)(b * Tt + seg * SEG + tile * 64 + tok) * Hh + h) * DhD + c4;
            *(float4*)&Ks[tok][c4] = *(const float4*)&g_k[g];
            *(float4*)&Vs[tok][c4] = *(const float4*)&g_v[g];
        }
        __syncthreads();
        int lim = t - tile * 64;
        if (lim >= 0) {
            int n = lim < 63 ? lim : 63;
            for (int tp = 0; tp <= n; tp++) {
                const float4* kr = (const float4*)Ks[tp];
                float a = 0.f;
#pragma unroll
                for (int j = 0; j < 16; j++) {
                    float4 k4 = kr[j];
                    a += q4r[j].x*k4.x + q4r[j].y*k4.y + q4r[j].z*k4.z + q4r[j].w*k4.w;
                }
                float f = wcur * a;
                const float4* vr = (const float4*)Vs[tp];
#pragma unroll
                for (int e = 0; e < 16; e++) {
                    float4 v4 = vr[e];
                    outr[4*e+0] += f * v4.x;
                    outr[4*e+1] += f * v4.y;
                    outr[4*e+2] += f * v4.z;
                    outr[4*e+3] += f * v4.w;
                }
            }
        }
    }

    float4* yp = (float4*)&g_y[rowbase];
#pragma unroll
    for (int e = 0; e < 16; e++)
        yp[e] = make_float4(outr[4*e], outr[4*e+1], outr[4*e+2], outr[4*e+3]);
}

// ---------------- launch ----------------------------------------------------
extern "C" void kernel_launch(void* const* d_in, const int* in_sizes, int n_in,
                              void* d_out, int out_size)
{
    const float* x  = (const float*)d_in[0];
    const float* Wq = (const float*)d_in[1];
    const float* Wk = (const float*)d_in[2];
    const float* Wv = (const float*)d_in[3];
    const float* Wu = (const float*)d_in[4];
    const float* Wo = (const float*)d_in[5];
    float* out = (float*)d_out;

    __nv_bfloat16 *pxh, *pxl, *pyh, *pyl;
    float* pyf;
    cudaGetSymbolAddress((void**)&pxh, g_xhi);
    cudaGetSymbolAddress((void**)&pxl, g_xlo);
    cudaGetSymbolAddress((void**)&pyh, g_yhi);
    cudaGetSymbolAddress((void**)&pyl, g_ylo);
    cudaGetSymbolAddress((void**)&pyf, g_y);

    cudaFuncSetAttribute(proj4_tc,    cudaFuncAttributeMaxDynamicSharedMemorySize, DYN_SMEM);
    cudaFuncSetAttribute(gemm_out_tc, cudaFuncAttributeMaxDynamicSharedMemorySize, DYN_SMEM);

    const int N4 = BT * Dd / 4;
    cvt_split<<<N4 / 256, 256>>>((const float4*)x, pxh, pxl, N4);

    dim3 gw(16, 16, 5);
    cvt_wt<<<gw, 256>>>(Wq, Wk, Wv, Wu, Wo);

    dim3 gp(Dd / 128, BT / 128, 4);                // (8, 64, 4)
    proj4_tc<<<gp, 256, DYN_SMEM>>>();

    seg_sums  <<<BH * NSEG, 256>>>();
    seg_prefix<<<BH,        256>>>();
    attn_kernel<<<BH * NSEG, 256>>>();

    cvt_split<<<N4 / 256, 256>>>((const float4*)pyf, pyh, pyl, N4);

    dim3 gg(Dd / 128, BT / 128);                   // (8, 64)
    gemm_out_tc<<<gg, 256, DYN_SMEM>>>(out);
}